// round 1
// baseline (speedup 1.0000x reference)
#include <cuda_runtime.h>
#include <cstdint>

// Problem constants (shape-fixed per problem instance)
#define DD    128
#define NMAX  50000
// GEMM smem: W tile 128x128 f32 (64KB) + X tile 128x128 f32 (64KB)
#define GEMM_SMEM_FLOATS (16384 + 16384)
#define GEMM_SMEM_BYTES  (GEMM_SMEM_FLOATS * 4)

// -------- scratch (allocation-free: __device__ globals) --------
// 4 node-feature buffers: xn (activated features), agg, h (post-GEMM1), xraw (post-GEMM2)
__device__ float g_bufs[4ull * NMAX * DD];
// [0:128) colsum  [128:256) colsumsq  [256:384) bn scale  [384:512) bn shift
__device__ __align__(16) float g_small[512];
__device__ int g_edge64;

// -------- tiny utility kernels --------
__global__ void zero_stats_kernel() {
    g_small[threadIdx.x] = 0.0f;   // 256 threads: zero sum + sumsq
}

// Detect whether edge_index is int64 or int32: for int64 (values < 2^31),
// every odd int32 word (high half) is zero.
__global__ void detect_kernel(const int* __restrict__ ei) {
    if (threadIdx.x == 0) {
        int ok = 1;
        for (int i = 0; i < 256; i++) {
            if (ei[2 * i + 1] != 0) { ok = 0; break; }
        }
        g_edge64 = ok;
    }
}

// prep: xn = act(raw)   (act = BN+ReLU for layers>0, identity for layer 0)
//       agg = (1+eps[layer]) * xn
__global__ void prep_kernel(const float* __restrict__ raw,
                            float* __restrict__ xn,
                            float* __restrict__ agg,
                            const float* __restrict__ epsArr,
                            int layer, int n, int doBN) {
    int idx = blockIdx.x * blockDim.x + threadIdx.x;   // float4 index
    int total = n * (DD / 4);
    if (idx >= total) return;
    float4 v = ((const float4*)raw)[idx];
    if (doBN) {
        int c4 = idx & 31;
        float4 s = ((const float4*)(g_small + 256))[c4];
        float4 t = ((const float4*)(g_small + 384))[c4];
        v.x = fmaxf(fmaf(v.x, s.x, t.x), 0.0f);
        v.y = fmaxf(fmaf(v.y, s.y, t.y), 0.0f);
        v.z = fmaxf(fmaf(v.z, s.z, t.z), 0.0f);
        v.w = fmaxf(fmaf(v.w, s.w, t.w), 0.0f);
    }
    ((float4*)xn)[idx] = v;
    float e = 1.0f + epsArr[layer];
    float4 a;
    a.x = v.x * e; a.y = v.y * e; a.z = v.z * e; a.w = v.w * e;
    ((float4*)agg)[idx] = a;
}

// scatter: one warp per edge; agg[dst] += xn[src] (128 floats = 32 lanes x float4)
__global__ void scatter_kernel(const float* __restrict__ xn,
                               float* __restrict__ agg,
                               const void* __restrict__ ei,
                               int E) {
    int wid = (blockIdx.x * blockDim.x + threadIdx.x) >> 5;
    int lane = threadIdx.x & 31;
    if (wid >= E) return;
    int s, d;
    if (g_edge64) {
        const long long* e64 = (const long long*)ei;
        s = (int)e64[wid];
        d = (int)e64[E + wid];
    } else {
        const int* e32 = (const int*)ei;
        s = e32[wid];
        d = e32[E + wid];
    }
    float4 v = ((const float4*)xn)[s * 32 + lane];
    float* p = agg + (size_t)d * DD + lane * 4;
    asm volatile("red.global.add.v4.f32 [%0], {%1,%2,%3,%4};"
                 :: "l"(p), "f"(v.x), "f"(v.y), "f"(v.z), "f"(v.w)
                 : "memory");
}

// GEMM: out[n,128] = act(A)[n,128] @ W[128,128] + bias
//   applyBN: apply BN(scale/shift from g_small)+ReLU to A while loading the tile
//   accumStats: accumulate per-column sum/sumsq of the OUTPUT into g_small[0:256)
// Block: 128 rows x 128 cols, full K=128 in smem. 256 threads, 8x8 thread tile.
__global__ __launch_bounds__(256, 1)
void gemm_kernel(const float* __restrict__ A,
                 const float* __restrict__ W,
                 const float* __restrict__ bias,
                 float* __restrict__ out,
                 int n, int applyBN, int accumStats) {
    extern __shared__ float smem[];
    float* ws = smem;            // [128][128]  W, row-major k x c
    float* xs = smem + 16384;    // [128][128]  A tile
    float4* ws4 = (float4*)ws;
    float4* xs4 = (float4*)xs;

    int tid = threadIdx.x;
    int tx = tid & 15;           // col group: cols 4tx..4tx+3 and 64+4tx..64+4tx+3
    int ty = tid >> 4;           // row group: rows ty*8 .. ty*8+7
    int rowBase = blockIdx.x << 7;

    // load W (16384 floats = 4096 float4)
    const float4* W4 = (const float4*)W;
#pragma unroll
    for (int i = 0; i < 16; i++) ws4[tid + 256 * i] = W4[tid + 256 * i];

    // load A tile (with optional BN+ReLU)
    const float4* A4 = (const float4*)A;
#pragma unroll
    for (int i = 0; i < 16; i++) {
        int li = tid + 256 * i;          // 0..4095
        int r = li >> 5;
        int c4 = li & 31;
        int grow = rowBase + r;
        float4 v = make_float4(0.f, 0.f, 0.f, 0.f);
        if (grow < n) v = A4[(size_t)grow * 32 + c4];
        if (applyBN) {
            float4 s = ((const float4*)(g_small + 256))[c4];
            float4 t = ((const float4*)(g_small + 384))[c4];
            v.x = fmaxf(fmaf(v.x, s.x, t.x), 0.0f);
            v.y = fmaxf(fmaf(v.y, s.y, t.y), 0.0f);
            v.z = fmaxf(fmaf(v.z, s.z, t.z), 0.0f);
            v.w = fmaxf(fmaf(v.w, s.w, t.w), 0.0f);
        }
        xs4[li] = v;
    }
    __syncthreads();

    float acc[8][8];
#pragma unroll
    for (int r = 0; r < 8; r++)
#pragma unroll
        for (int c = 0; c < 8; c++) acc[r][c] = 0.0f;

#pragma unroll 2
    for (int k = 0; k < 128; k += 4) {
        float a[8][4];
#pragma unroll
        for (int r = 0; r < 8; r++) {
            float4 av = xs4[(ty * 8 + r) * 32 + (k >> 2)];
            a[r][0] = av.x; a[r][1] = av.y; a[r][2] = av.z; a[r][3] = av.w;
        }
#pragma unroll
        for (int kk = 0; kk < 4; kk++) {
            float4 w0 = ws4[(k + kk) * 32 + tx];
            float4 w1 = ws4[(k + kk) * 32 + tx + 16];
            float wv[8] = {w0.x, w0.y, w0.z, w0.w, w1.x, w1.y, w1.z, w1.w};
#pragma unroll
            for (int r = 0; r < 8; r++) {
#pragma unroll
                for (int c = 0; c < 8; c++)
                    acc[r][c] = fmaf(a[r][kk], wv[c], acc[r][c]);
            }
        }
    }

    // epilogue: bias add, store, per-column stats partials
    float4 b0 = ((const float4*)bias)[tx];
    float4 b1v = ((const float4*)bias)[tx + 16];
    float bv[8] = {b0.x, b0.y, b0.z, b0.w, b1v.x, b1v.y, b1v.z, b1v.w};

    float psum[8], psq[8];
#pragma unroll
    for (int c = 0; c < 8; c++) { psum[c] = 0.0f; psq[c] = 0.0f; }

#pragma unroll
    for (int r = 0; r < 8; r++) {
        int grow = rowBase + ty * 8 + r;
        if (grow < n) {
            float o[8];
#pragma unroll
            for (int c = 0; c < 8; c++) o[c] = acc[r][c] + bv[c];
            float4 s0 = make_float4(o[0], o[1], o[2], o[3]);
            float4 s1 = make_float4(o[4], o[5], o[6], o[7]);
            ((float4*)out)[(size_t)grow * 32 + tx] = s0;
            ((float4*)out)[(size_t)grow * 32 + tx + 16] = s1;
            if (accumStats) {
#pragma unroll
                for (int c = 0; c < 8; c++) {
                    psum[c] += o[c];
                    psq[c] += o[c] * o[c];
                }
            }
        }
    }

    if (accumStats) {
        __syncthreads();                 // done with ws/xs; reuse ws as reduce buffer
        float* redS = ws;                // [16][128]
        float* redQ = ws + 2048;         // [16][128]
        ((float4*)&redS[ty * 128])[tx]      = make_float4(psum[0], psum[1], psum[2], psum[3]);
        ((float4*)&redS[ty * 128])[tx + 16] = make_float4(psum[4], psum[5], psum[6], psum[7]);
        ((float4*)&redQ[ty * 128])[tx]      = make_float4(psq[0], psq[1], psq[2], psq[3]);
        ((float4*)&redQ[ty * 128])[tx + 16] = make_float4(psq[4], psq[5], psq[6], psq[7]);
        __syncthreads();
        if (tid < 128) {
            float s = 0.0f;
#pragma unroll
            for (int t = 0; t < 16; t++) s += redS[t * 128 + tid];
            atomicAdd(&g_small[tid], s);
        } else {
            int c = tid - 128;
            float q = 0.0f;
#pragma unroll
            for (int t = 0; t < 16; t++) q += redQ[t * 128 + c];
            atomicAdd(&g_small[128 + c], q);
        }
    }
}

// turn accumulated sum/sumsq into BN scale/shift; re-zero stats for next use
__global__ void bnparams_kernel(const float* __restrict__ gamma,
                                const float* __restrict__ beta,
                                float invN) {
    int c = threadIdx.x;   // 128 threads
    float mean = g_small[c] * invN;
    float var = g_small[128 + c] * invN - mean * mean;
    float sc = gamma[c] * rsqrtf(fmaxf(var, 0.0f) + 1e-5f);
    g_small[256 + c] = sc;
    g_small[384 + c] = beta[c] - mean * sc;
    g_small[c] = 0.0f;
    g_small[128 + c] = 0.0f;
}

extern "C" void kernel_launch(void* const* d_in, const int* in_sizes, int n_in,
                              void* d_out, int out_size) {
    const float* x     = (const float*)d_in[0];
    const void*  ei    = d_in[1];
    const float* eps   = (const float*)d_in[2];
    const float* W1    = (const float*)d_in[3];
    const float* b1    = (const float*)d_in[4];
    const float* g1    = (const float*)d_in[5];
    const float* beta1 = (const float*)d_in[6];
    const float* W2    = (const float*)d_in[7];
    const float* b2    = (const float*)d_in[8];
    const float* bng   = (const float*)d_in[9];
    const float* bnb   = (const float*)d_in[10];
    float* out = (float*)d_out;

    int n = in_sizes[0] / DD;
    int E = in_sizes[1] / 2;

    float* bufs = nullptr;
    cudaGetSymbolAddress((void**)&bufs, g_bufs);
    float* xn   = bufs;
    float* agg  = bufs + (size_t)1 * NMAX * DD;
    float* h    = bufs + (size_t)2 * NMAX * DD;
    float* xraw = bufs + (size_t)3 * NMAX * DD;

    cudaFuncSetAttribute((const void*)gemm_kernel,
                         cudaFuncAttributeMaxDynamicSharedMemorySize, GEMM_SMEM_BYTES);

    zero_stats_kernel<<<1, 256>>>();
    detect_kernel<<<1, 32>>>((const int*)ei);

    int prepBlocks = (n * (DD / 4) + 255) / 256;
    int scatBlocks = (E + 7) / 8;          // 8 warps/block, 1 edge/warp
    int gemmBlocks = (n + 127) / 128;
    float invN = 1.0f / (float)n;

    const float* cur_raw = x;
    for (int layer = 0; layer < 3; layer++) {
        int doBN = (layer > 0) ? 1 : 0;
        prep_kernel<<<prepBlocks, 256>>>(cur_raw, xn, agg, eps, layer, n, doBN);
        scatter_kernel<<<scatBlocks, 256>>>(xn, agg, ei, E);
        gemm_kernel<<<gemmBlocks, 256, GEMM_SMEM_BYTES>>>(
            agg, W1 + (size_t)layer * DD * DD, b1 + layer * DD, h, n, 0, 1);
        bnparams_kernel<<<1, 128>>>(g1 + layer * DD, beta1 + layer * DD, invN);
        int last = (layer == 2);
        float* o = last ? out : xraw;
        gemm_kernel<<<gemmBlocks, 256, GEMM_SMEM_BYTES>>>(
            h, W2 + (size_t)layer * DD * DD, b2 + layer * DD, o, n, 1, last ? 0 : 1);
        if (!last)
            bnparams_kernel<<<1, 128>>>(bng + layer * DD, bnb + layer * DD, invN);
        cur_raw = xraw;
    }
}

// round 4
// speedup vs baseline: 1.4747x; 1.4747x over previous
#include <cuda_runtime.h>
#include <cstdint>

// Problem constants (shape-fixed per problem instance)
#define DD    128
#define NMAX  50000
#define EMAX  800000
#define GEMM_SMEM_FLOATS (16384 + 16384)
#define GEMM_SMEM_BYTES  (GEMM_SMEM_FLOATS * 4)

// -------- scratch (allocation-free: __device__ globals) --------
__device__ float g_bufs[4ull * NMAX * DD];  // xn, agg, h, xraw
// [0:128) colsum  [128:256) colsumsq  [256:384) bn scale  [384:512) bn shift
__device__ __align__(16) float g_small[512];
__device__ int g_edge64;
// CSR scratch
__device__ int g_sorted_src[EMAX];
__device__ int g_rowoff[NMAX + 1];   // becomes END offsets after placement
__device__ int g_counts[NMAX];
__device__ int g_partials[1024];

// -------- tiny utility kernels --------
__global__ void zero_stats_kernel() {
    g_small[threadIdx.x] = 0.0f;   // 256 threads
}

__global__ void zero_counts_kernel(int n) {
    int i = blockIdx.x * blockDim.x + threadIdx.x;
    if (i < n) g_counts[i] = 0;
}

// Detect int64 vs int32 edge_index (int64 node ids < 2^31 -> odd words zero)
__global__ void detect_kernel(const int* __restrict__ ei) {
    if (threadIdx.x == 0) {
        int ok = 1;
        for (int i = 0; i < 256; i++) {
            if (ei[2 * i + 1] != 0) { ok = 0; break; }
        }
        g_edge64 = ok;
    }
}

__device__ __forceinline__ void load_edge(const void* ei, int E, int e,
                                          int& s, int& d) {
    if (g_edge64) {
        const long long* e64 = (const long long*)ei;
        s = (int)e64[e];
        d = (int)e64[E + e];
    } else {
        const int* e32 = (const int*)ei;
        s = e32[e];
        d = e32[E + e];
    }
}

// ---- counting sort of edges by dst (built once per launch) ----
__global__ void hist_kernel(const void* __restrict__ ei, int E) {
    int e = blockIdx.x * blockDim.x + threadIdx.x;
    if (e >= E) return;
    int s, d;
    load_edge(ei, E, e, s, d);
    atomicAdd(&g_counts[d], 1);
}

// block-local exclusive scan of counts -> g_rowoff; block sums -> g_partials
__global__ void scanA_kernel(int n) {
    __shared__ int sm[256];
    int t = threadIdx.x;
    int i = blockIdx.x * 256 + t;
    int v = (i < n) ? g_counts[i] : 0;
    sm[t] = v;
    __syncthreads();
#pragma unroll
    for (int off = 1; off < 256; off <<= 1) {
        int add = (t >= off) ? sm[t - off] : 0;
        __syncthreads();
        sm[t] += add;
        __syncthreads();
    }
    if (i < n) g_rowoff[i] = sm[t] - v;       // exclusive, block-local
    if (t == 255) g_partials[blockIdx.x] = sm[t];
}

// exclusive scan of block partials (NB <= 1024), single block of 1024
__global__ void scanB_kernel(int nb) {
    __shared__ int sm[1024];
    int t = threadIdx.x;
    int v = (t < nb) ? g_partials[t] : 0;
    sm[t] = v;
    __syncthreads();
#pragma unroll
    for (int off = 1; off < 1024; off <<= 1) {
        int add = (t >= off) ? sm[t - off] : 0;
        __syncthreads();
        sm[t] += add;
        __syncthreads();
    }
    if (t < nb) g_partials[t] = sm[t] - v;    // exclusive
}

__global__ void scanC_kernel(int n) {
    int i = blockIdx.x * blockDim.x + threadIdx.x;
    if (i < n) g_rowoff[i] += g_partials[blockIdx.x * 256 / 256 == 0 ? blockIdx.x : blockIdx.x]; // blk idx
}

// (scanC simplified below — one thread block per 256 elements, same tiling as scanA)
__global__ void scanC2_kernel(int n) {
    int i = blockIdx.x * 256 + threadIdx.x;
    if (i < n) g_rowoff[i] += g_partials[blockIdx.x];
}

// place edges: pos = old rowoff cursor; rowoff becomes END offsets afterwards
__global__ void place_kernel(const void* __restrict__ ei, int E) {
    int e = blockIdx.x * blockDim.x + threadIdx.x;
    if (e >= E) return;
    int s, d;
    load_edge(ei, E, e, s, d);
    int pos = atomicAdd(&g_rowoff[d], 1);
    g_sorted_src[pos] = s;
}

// prep: xn = BN+ReLU(raw) for layers > 0 (layer 0 uses x directly)
__global__ void prep_kernel(const float* __restrict__ raw,
                            float* __restrict__ xn, int n) {
    int idx = blockIdx.x * blockDim.x + threadIdx.x;   // float4 index
    int total = n * (DD / 4);
    if (idx >= total) return;
    float4 v = ((const float4*)raw)[idx];
    int c4 = idx & 31;
    float4 s = ((const float4*)(g_small + 256))[c4];
    float4 t = ((const float4*)(g_small + 384))[c4];
    v.x = fmaxf(fmaf(v.x, s.x, t.x), 0.0f);
    v.y = fmaxf(fmaf(v.y, s.y, t.y), 0.0f);
    v.z = fmaxf(fmaf(v.z, s.z, t.z), 0.0f);
    v.w = fmaxf(fmaf(v.w, s.w, t.w), 0.0f);
    ((float4*)xn)[idx] = v;
}

// gather aggregation: one warp per dst node.
// agg[i] = (1+eps)*xn[i] + sum_{e in CSR row i} xn[src[e]]
__global__ void agg_kernel(const float* __restrict__ xn,
                           float* __restrict__ agg,
                           const float* __restrict__ epsArr,
                           int layer, int n) {
    int node = (blockIdx.x * blockDim.x + threadIdx.x) >> 5;
    int lane = threadIdx.x & 31;
    if (node >= n) return;
    int start = (node == 0) ? 0 : g_rowoff[node - 1];
    int end = g_rowoff[node];
    const float4* X4 = (const float4*)xn;
    float e1 = 1.0f + epsArr[layer];
    float4 self = X4[(size_t)node * 32 + lane];
    float ax = self.x * e1, ay = self.y * e1, az = self.z * e1, aw = self.w * e1;
    int e = start;
    for (; e + 4 <= end; e += 4) {
        int s0 = g_sorted_src[e];
        int s1 = g_sorted_src[e + 1];
        int s2 = g_sorted_src[e + 2];
        int s3 = g_sorted_src[e + 3];
        float4 v0 = X4[(size_t)s0 * 32 + lane];
        float4 v1 = X4[(size_t)s1 * 32 + lane];
        float4 v2 = X4[(size_t)s2 * 32 + lane];
        float4 v3 = X4[(size_t)s3 * 32 + lane];
        ax += v0.x + v1.x + v2.x + v3.x;
        ay += v0.y + v1.y + v2.y + v3.y;
        az += v0.z + v1.z + v2.z + v3.z;
        aw += v0.w + v1.w + v2.w + v3.w;
    }
    for (; e < end; e++) {
        int s0 = g_sorted_src[e];
        float4 v0 = X4[(size_t)s0 * 32 + lane];
        ax += v0.x; ay += v0.y; az += v0.z; aw += v0.w;
    }
    ((float4*)agg)[(size_t)node * 32 + lane] = make_float4(ax, ay, az, aw);
}

// GEMM: out[n,128] = act(A)[n,128] @ W[128,128] + bias  (as round 1)
__global__ __launch_bounds__(256, 1)
void gemm_kernel(const float* __restrict__ A,
                 const float* __restrict__ W,
                 const float* __restrict__ bias,
                 float* __restrict__ out,
                 int n, int applyBN, int accumStats) {
    extern __shared__ float smem[];
    float* ws = smem;
    float* xs = smem + 16384;
    float4* ws4 = (float4*)ws;
    float4* xs4 = (float4*)xs;

    int tid = threadIdx.x;
    int tx = tid & 15;
    int ty = tid >> 4;
    int rowBase = blockIdx.x << 7;

    const float4* W4 = (const float4*)W;
#pragma unroll
    for (int i = 0; i < 16; i++) ws4[tid + 256 * i] = W4[tid + 256 * i];

    const float4* A4 = (const float4*)A;
#pragma unroll
    for (int i = 0; i < 16; i++) {
        int li = tid + 256 * i;
        int r = li >> 5;
        int c4 = li & 31;
        int grow = rowBase + r;
        float4 v = make_float4(0.f, 0.f, 0.f, 0.f);
        if (grow < n) v = A4[(size_t)grow * 32 + c4];
        if (applyBN) {
            float4 s = ((const float4*)(g_small + 256))[c4];
            float4 t = ((const float4*)(g_small + 384))[c4];
            v.x = fmaxf(fmaf(v.x, s.x, t.x), 0.0f);
            v.y = fmaxf(fmaf(v.y, s.y, t.y), 0.0f);
            v.z = fmaxf(fmaf(v.z, s.z, t.z), 0.0f);
            v.w = fmaxf(fmaf(v.w, s.w, t.w), 0.0f);
        }
        xs4[li] = v;
    }
    __syncthreads();

    float acc[8][8];
#pragma unroll
    for (int r = 0; r < 8; r++)
#pragma unroll
        for (int c = 0; c < 8; c++) acc[r][c] = 0.0f;

#pragma unroll 2
    for (int k = 0; k < 128; k += 4) {
        float a[8][4];
#pragma unroll
        for (int r = 0; r < 8; r++) {
            float4 av = xs4[(ty * 8 + r) * 32 + (k >> 2)];
            a[r][0] = av.x; a[r][1] = av.y; a[r][2] = av.z; a[r][3] = av.w;
        }
#pragma unroll
        for (int kk = 0; kk < 4; kk++) {
            float4 w0 = ws4[(k + kk) * 32 + tx];
            float4 w1 = ws4[(k + kk) * 32 + tx + 16];
            float wv[8] = {w0.x, w0.y, w0.z, w0.w, w1.x, w1.y, w1.z, w1.w};
#pragma unroll
            for (int r = 0; r < 8; r++) {
#pragma unroll
                for (int c = 0; c < 8; c++)
                    acc[r][c] = fmaf(a[r][kk], wv[c], acc[r][c]);
            }
        }
    }

    float4 b0 = ((const float4*)bias)[tx];
    float4 b1v = ((const float4*)bias)[tx + 16];
    float bv[8] = {b0.x, b0.y, b0.z, b0.w, b1v.x, b1v.y, b1v.z, b1v.w};

    float psum[8], psq[8];
#pragma unroll
    for (int c = 0; c < 8; c++) { psum[c] = 0.0f; psq[c] = 0.0f; }

#pragma unroll
    for (int r = 0; r < 8; r++) {
        int grow = rowBase + ty * 8 + r;
        if (grow < n) {
            float o[8];
#pragma unroll
            for (int c = 0; c < 8; c++) o[c] = acc[r][c] + bv[c];
            ((float4*)out)[(size_t)grow * 32 + tx] = make_float4(o[0], o[1], o[2], o[3]);
            ((float4*)out)[(size_t)grow * 32 + tx + 16] = make_float4(o[4], o[5], o[6], o[7]);
            if (accumStats) {
#pragma unroll
                for (int c = 0; c < 8; c++) {
                    psum[c] += o[c];
                    psq[c] += o[c] * o[c];
                }
            }
        }
    }

    if (accumStats) {
        __syncthreads();
        float* redS = ws;
        float* redQ = ws + 2048;
        ((float4*)&redS[ty * 128])[tx]      = make_float4(psum[0], psum[1], psum[2], psum[3]);
        ((float4*)&redS[ty * 128])[tx + 16] = make_float4(psum[4], psum[5], psum[6], psum[7]);
        ((float4*)&redQ[ty * 128])[tx]      = make_float4(psq[0], psq[1], psq[2], psq[3]);
        ((float4*)&redQ[ty * 128])[tx + 16] = make_float4(psq[4], psq[5], psq[6], psq[7]);
        __syncthreads();
        if (tid < 128) {
            float s = 0.0f;
#pragma unroll
            for (int t = 0; t < 16; t++) s += redS[t * 128 + tid];
            atomicAdd(&g_small[tid], s);
        } else {
            int c = tid - 128;
            float q = 0.0f;
#pragma unroll
            for (int t = 0; t < 16; t++) q += redQ[t * 128 + c];
            atomicAdd(&g_small[128 + c], q);
        }
    }
}

__global__ void bnparams_kernel(const float* __restrict__ gamma,
                                const float* __restrict__ beta,
                                float invN) {
    int c = threadIdx.x;
    float mean = g_small[c] * invN;
    float var = g_small[128 + c] * invN - mean * mean;
    float sc = gamma[c] * rsqrtf(fmaxf(var, 0.0f) + 1e-5f);
    g_small[256 + c] = sc;
    g_small[384 + c] = beta[c] - mean * sc;
    g_small[c] = 0.0f;
    g_small[128 + c] = 0.0f;
}

extern "C" void kernel_launch(void* const* d_in, const int* in_sizes, int n_in,
                              void* d_out, int out_size) {
    const float* x     = (const float*)d_in[0];
    const void*  ei    = d_in[1];
    const float* eps   = (const float*)d_in[2];
    const float* W1    = (const float*)d_in[3];
    const float* b1    = (const float*)d_in[4];
    const float* g1    = (const float*)d_in[5];
    const float* beta1 = (const float*)d_in[6];
    const float* W2    = (const float*)d_in[7];
    const float* b2    = (const float*)d_in[8];
    const float* bng   = (const float*)d_in[9];
    const float* bnb   = (const float*)d_in[10];
    float* out = (float*)d_out;

    int n = in_sizes[0] / DD;
    int E = in_sizes[1] / 2;

    float* bufs = nullptr;
    cudaGetSymbolAddress((void**)&bufs, g_bufs);
    float* xn   = bufs;
    float* agg  = bufs + (size_t)1 * NMAX * DD;
    float* h    = bufs + (size_t)2 * NMAX * DD;
    float* xraw = bufs + (size_t)3 * NMAX * DD;

    cudaFuncSetAttribute((const void*)gemm_kernel,
                         cudaFuncAttributeMaxDynamicSharedMemorySize, GEMM_SMEM_BYTES);

    int nb256 = (n + 255) / 256;
    int eb256 = (E + 255) / 256;

    // --- one-time per launch: stats zero, dtype detect, CSR build ---
    zero_stats_kernel<<<1, 256>>>();
    detect_kernel<<<1, 32>>>((const int*)ei);
    zero_counts_kernel<<<nb256, 256>>>(n);
    hist_kernel<<<eb256, 256>>>(ei, E);
    scanA_kernel<<<nb256, 256>>>(n);
    scanB_kernel<<<1, 1024>>>(nb256);
    scanC2_kernel<<<nb256, 256>>>(n);
    place_kernel<<<eb256, 256>>>(ei, E);

    int prepBlocks = (n * (DD / 4) + 255) / 256;
    int aggBlocks = (n + 7) / 8;           // 8 warps/block, 1 node/warp
    int gemmBlocks = (n + 127) / 128;
    float invN = 1.0f / (float)n;

    const float* cur = x;   // activated features for this layer
    for (int layer = 0; layer < 3; layer++) {
        if (layer > 0) {
            prep_kernel<<<prepBlocks, 256>>>(xraw, xn, n);
            cur = xn;
        }
        agg_kernel<<<aggBlocks, 256>>>(cur, agg, eps, layer, n);
        gemm_kernel<<<gemmBlocks, 256, GEMM_SMEM_BYTES>>>(
            agg, W1 + (size_t)layer * DD * DD, b1 + layer * DD, h, n, 0, 1);
        bnparams_kernel<<<1, 128>>>(g1 + layer * DD, beta1 + layer * DD, invN);
        int last = (layer == 2);
        float* o = last ? out : xraw;
        gemm_kernel<<<gemmBlocks, 256, GEMM_SMEM_BYTES>>>(
            h, W2 + (size_t)layer * DD * DD, b2 + layer * DD, o, n, 1, last ? 0 : 1);
        if (!last)
            bnparams_kernel<<<1, 128>>>(bng + layer * DD, bnb + layer * DD, invN);
    }
}

// round 5
// speedup vs baseline: 1.5258x; 1.0346x over previous
#include <cuda_runtime.h>
#include <cstdint>

// Problem constants (shape-fixed per problem instance)
#define DD    128
#define NMAX  50000
#define EMAX  800000
#define GEMM_SMEM_FLOATS (16384 + 16384)
#define GEMM_SMEM_BYTES  (GEMM_SMEM_FLOATS * 4)

// -------- scratch (allocation-free: __device__ globals) --------
__device__ float g_bufs[4ull * NMAX * DD];  // xn, agg, h, xraw
// [0:128) colsum  [128:256) colsumsq  [256:384) bn scale  [384:512) bn shift
__device__ __align__(16) float g_small[512];
__device__ int g_edge64;
// CSR scratch
__device__ int g_sorted_src[EMAX];
__device__ int g_rowoff[NMAX + 1];   // becomes END offsets after placement
__device__ int g_counts[NMAX];
__device__ int g_partials[1024];

// -------- tiny utility kernels --------
__global__ void zero_stats_kernel() {
    g_small[threadIdx.x] = 0.0f;   // 256 threads
}

__global__ void zero_counts_kernel(int n) {
    int i = blockIdx.x * blockDim.x + threadIdx.x;
    if (i < n) g_counts[i] = 0;
}

// Detect int64 vs int32 edge_index (int64 node ids < 2^31 -> odd words zero)
__global__ void detect_kernel(const int* __restrict__ ei) {
    if (threadIdx.x == 0) {
        int ok = 1;
        for (int i = 0; i < 256; i++) {
            if (ei[2 * i + 1] != 0) { ok = 0; break; }
        }
        g_edge64 = ok;
    }
}

__device__ __forceinline__ void load_edge(const void* ei, int E, int e,
                                          int& s, int& d) {
    if (g_edge64) {
        const long long* e64 = (const long long*)ei;
        s = (int)e64[e];
        d = (int)e64[E + e];
    } else {
        const int* e32 = (const int*)ei;
        s = e32[e];
        d = e32[E + e];
    }
}

// ---- counting sort of edges by dst (built once per launch) ----
__global__ void hist_kernel(const void* __restrict__ ei, int E) {
    int e = blockIdx.x * blockDim.x + threadIdx.x;
    if (e >= E) return;
    int s, d;
    load_edge(ei, E, e, s, d);
    atomicAdd(&g_counts[d], 1);
}

// block-local exclusive scan of counts -> g_rowoff; block sums -> g_partials
__global__ void scanA_kernel(int n) {
    __shared__ int sm[256];
    int t = threadIdx.x;
    int i = blockIdx.x * 256 + t;
    int v = (i < n) ? g_counts[i] : 0;
    sm[t] = v;
    __syncthreads();
#pragma unroll
    for (int off = 1; off < 256; off <<= 1) {
        int add = (t >= off) ? sm[t - off] : 0;
        __syncthreads();
        sm[t] += add;
        __syncthreads();
    }
    if (i < n) g_rowoff[i] = sm[t] - v;       // exclusive, block-local
    if (t == 255) g_partials[blockIdx.x] = sm[t];
}

// exclusive scan of block partials (NB <= 1024), single block of 1024
__global__ void scanB_kernel(int nb) {
    __shared__ int sm[1024];
    int t = threadIdx.x;
    int v = (t < nb) ? g_partials[t] : 0;
    sm[t] = v;
    __syncthreads();
#pragma unroll
    for (int off = 1; off < 1024; off <<= 1) {
        int add = (t >= off) ? sm[t - off] : 0;
        __syncthreads();
        sm[t] += add;
        __syncthreads();
    }
    if (t < nb) g_partials[t] = sm[t] - v;    // exclusive
}

__global__ void scanC2_kernel(int n) {
    int i = blockIdx.x * 256 + threadIdx.x;
    if (i < n) g_rowoff[i] += g_partials[blockIdx.x];
}

// place edges: pos = old rowoff cursor; rowoff becomes END offsets afterwards
__global__ void place_kernel(const void* __restrict__ ei, int E) {
    int e = blockIdx.x * blockDim.x + threadIdx.x;
    if (e >= E) return;
    int s, d;
    load_edge(ei, E, e, s, d);
    int pos = atomicAdd(&g_rowoff[d], 1);
    g_sorted_src[pos] = s;
}

// prep: xn = BN+ReLU(raw) for layers > 0 (layer 0 uses x directly)
__global__ void prep_kernel(const float* __restrict__ raw,
                            float* __restrict__ xn, int n) {
    int idx = blockIdx.x * blockDim.x + threadIdx.x;   // float4 index
    int total = n * (DD / 4);
    if (idx >= total) return;
    float4 v = ((const float4*)raw)[idx];
    int c4 = idx & 31;
    float4 s = ((const float4*)(g_small + 256))[c4];
    float4 t = ((const float4*)(g_small + 384))[c4];
    v.x = fmaxf(fmaf(v.x, s.x, t.x), 0.0f);
    v.y = fmaxf(fmaf(v.y, s.y, t.y), 0.0f);
    v.z = fmaxf(fmaf(v.z, s.z, t.z), 0.0f);
    v.w = fmaxf(fmaf(v.w, s.w, t.w), 0.0f);
    ((float4*)xn)[idx] = v;
}

// gather aggregation: one warp per dst node.
// agg[i] = (1+eps)*xn[i] + sum_{e in CSR row i} xn[src[e]]
__global__ void agg_kernel(const float* __restrict__ xn,
                           float* __restrict__ agg,
                           const float* __restrict__ epsArr,
                           int layer, int n) {
    int node = (blockIdx.x * blockDim.x + threadIdx.x) >> 5;
    int lane = threadIdx.x & 31;
    if (node >= n) return;
    int start = (node == 0) ? 0 : g_rowoff[node - 1];
    int end = g_rowoff[node];
    const float4* X4 = (const float4*)xn;
    float e1 = 1.0f + epsArr[layer];
    float4 self = X4[(size_t)node * 32 + lane];
    float ax = self.x * e1, ay = self.y * e1, az = self.z * e1, aw = self.w * e1;
    int e = start;
    for (; e + 4 <= end; e += 4) {
        int s0 = g_sorted_src[e];
        int s1 = g_sorted_src[e + 1];
        int s2 = g_sorted_src[e + 2];
        int s3 = g_sorted_src[e + 3];
        float4 v0 = X4[(size_t)s0 * 32 + lane];
        float4 v1 = X4[(size_t)s1 * 32 + lane];
        float4 v2 = X4[(size_t)s2 * 32 + lane];
        float4 v3 = X4[(size_t)s3 * 32 + lane];
        ax += v0.x + v1.x + v2.x + v3.x;
        ay += v0.y + v1.y + v2.y + v3.y;
        az += v0.z + v1.z + v2.z + v3.z;
        aw += v0.w + v1.w + v2.w + v3.w;
    }
    for (; e < end; e++) {
        int s0 = g_sorted_src[e];
        float4 v0 = X4[(size_t)s0 * 32 + lane];
        ax += v0.x; ay += v0.y; az += v0.z; aw += v0.w;
    }
    ((float4*)agg)[(size_t)node * 32 + lane] = make_float4(ax, ay, az, aw);
}

// GEMM: out[n,128] = act(A)[n,128] @ W[128,128] + bias
// Inner loop uses Blackwell packed fp32 FMA (fma.rn.f32x2): 8x8 thread tile
// held as 8x4 packed-pair (b64) accumulators -> 2x FMA lanes per fma-pipe issue.
__global__ __launch_bounds__(256, 1)
void gemm_kernel(const float* __restrict__ A,
                 const float* __restrict__ W,
                 const float* __restrict__ bias,
                 float* __restrict__ out,
                 int n, int applyBN, int accumStats) {
    extern __shared__ float smem[];
    float* ws = smem;
    float* xs = smem + 16384;
    float4* ws4 = (float4*)ws;
    float4* xs4 = (float4*)xs;

    int tid = threadIdx.x;
    int tx = tid & 15;
    int ty = tid >> 4;
    int rowBase = blockIdx.x << 7;

    const float4* W4 = (const float4*)W;
#pragma unroll
    for (int i = 0; i < 16; i++) ws4[tid + 256 * i] = W4[tid + 256 * i];

    const float4* A4 = (const float4*)A;
#pragma unroll
    for (int i = 0; i < 16; i++) {
        int li = tid + 256 * i;
        int r = li >> 5;
        int c4 = li & 31;
        int grow = rowBase + r;
        float4 v = make_float4(0.f, 0.f, 0.f, 0.f);
        if (grow < n) v = A4[(size_t)grow * 32 + c4];
        if (applyBN) {
            float4 s = ((const float4*)(g_small + 256))[c4];
            float4 t = ((const float4*)(g_small + 384))[c4];
            v.x = fmaxf(fmaf(v.x, s.x, t.x), 0.0f);
            v.y = fmaxf(fmaf(v.y, s.y, t.y), 0.0f);
            v.z = fmaxf(fmaf(v.z, s.z, t.z), 0.0f);
            v.w = fmaxf(fmaf(v.w, s.w, t.w), 0.0f);
        }
        xs4[li] = v;
    }
    __syncthreads();

    // packed accumulators: acc2[r][p] = cols pair p of
    // { (4tx,4tx+1),(4tx+2,4tx+3),(64+4tx,64+4tx+1),(64+4tx+2,64+4tx+3) }
    unsigned long long acc2[8][4];
#pragma unroll
    for (int r = 0; r < 8; r++)
#pragma unroll
        for (int c = 0; c < 4; c++) acc2[r][c] = 0ull;

#pragma unroll 2
    for (int k = 0; k < 128; k += 4) {
        float a[8][4];
#pragma unroll
        for (int r = 0; r < 8; r++) {
            float4 av = xs4[(ty * 8 + r) * 32 + (k >> 2)];
            a[r][0] = av.x; a[r][1] = av.y; a[r][2] = av.z; a[r][3] = av.w;
        }
#pragma unroll
        for (int kk = 0; kk < 4; kk++) {
            float4 w0 = ws4[(k + kk) * 32 + tx];
            float4 w1 = ws4[(k + kk) * 32 + tx + 16];
            unsigned long long w2[4];
            asm("mov.b64 %0, {%1, %2};" : "=l"(w2[0]) : "f"(w0.x), "f"(w0.y));
            asm("mov.b64 %0, {%1, %2};" : "=l"(w2[1]) : "f"(w0.z), "f"(w0.w));
            asm("mov.b64 %0, {%1, %2};" : "=l"(w2[2]) : "f"(w1.x), "f"(w1.y));
            asm("mov.b64 %0, {%1, %2};" : "=l"(w2[3]) : "f"(w1.z), "f"(w1.w));
#pragma unroll
            for (int r = 0; r < 8; r++) {
                unsigned long long a2;
                asm("mov.b64 %0, {%1, %1};" : "=l"(a2) : "f"(a[r][kk]));
#pragma unroll
                for (int c = 0; c < 4; c++)
                    asm("fma.rn.f32x2 %0, %1, %2, %0;"
                        : "+l"(acc2[r][c]) : "l"(a2), "l"(w2[c]));
            }
        }
    }

    float4 b0 = ((const float4*)bias)[tx];
    float4 b1v = ((const float4*)bias)[tx + 16];
    float bv[8] = {b0.x, b0.y, b0.z, b0.w, b1v.x, b1v.y, b1v.z, b1v.w};

    float psum[8], psq[8];
#pragma unroll
    for (int c = 0; c < 8; c++) { psum[c] = 0.0f; psq[c] = 0.0f; }

#pragma unroll
    for (int r = 0; r < 8; r++) {
        int grow = rowBase + ty * 8 + r;
        if (grow < n) {
            float o[8];
#pragma unroll
            for (int c = 0; c < 4; c++) {
                float lo, hi;
                asm("mov.b64 {%0, %1}, %2;" : "=f"(lo), "=f"(hi) : "l"(acc2[r][c]));
                o[2 * c] = lo + bv[2 * c];
                o[2 * c + 1] = hi + bv[2 * c + 1];
            }
            ((float4*)out)[(size_t)grow * 32 + tx] = make_float4(o[0], o[1], o[2], o[3]);
            ((float4*)out)[(size_t)grow * 32 + tx + 16] = make_float4(o[4], o[5], o[6], o[7]);
            if (accumStats) {
#pragma unroll
                for (int c = 0; c < 8; c++) {
                    psum[c] += o[c];
                    psq[c] += o[c] * o[c];
                }
            }
        }
    }

    if (accumStats) {
        __syncthreads();
        float* redS = ws;
        float* redQ = ws + 2048;
        ((float4*)&redS[ty * 128])[tx]      = make_float4(psum[0], psum[1], psum[2], psum[3]);
        ((float4*)&redS[ty * 128])[tx + 16] = make_float4(psum[4], psum[5], psum[6], psum[7]);
        ((float4*)&redQ[ty * 128])[tx]      = make_float4(psq[0], psq[1], psq[2], psq[3]);
        ((float4*)&redQ[ty * 128])[tx + 16] = make_float4(psq[4], psq[5], psq[6], psq[7]);
        __syncthreads();
        if (tid < 128) {
            float s = 0.0f;
#pragma unroll
            for (int t = 0; t < 16; t++) s += redS[t * 128 + tid];
            atomicAdd(&g_small[tid], s);
        } else {
            int c = tid - 128;
            float q = 0.0f;
#pragma unroll
            for (int t = 0; t < 16; t++) q += redQ[t * 128 + c];
            atomicAdd(&g_small[128 + c], q);
        }
    }
}

__global__ void bnparams_kernel(const float* __restrict__ gamma,
                                const float* __restrict__ beta,
                                float invN) {
    int c = threadIdx.x;
    float mean = g_small[c] * invN;
    float var = g_small[128 + c] * invN - mean * mean;
    float sc = gamma[c] * rsqrtf(fmaxf(var, 0.0f) + 1e-5f);
    g_small[256 + c] = sc;
    g_small[384 + c] = beta[c] - mean * sc;
    g_small[c] = 0.0f;
    g_small[128 + c] = 0.0f;
}

extern "C" void kernel_launch(void* const* d_in, const int* in_sizes, int n_in,
                              void* d_out, int out_size) {
    const float* x     = (const float*)d_in[0];
    const void*  ei    = d_in[1];
    const float* eps   = (const float*)d_in[2];
    const float* W1    = (const float*)d_in[3];
    const float* b1    = (const float*)d_in[4];
    const float* g1    = (const float*)d_in[5];
    const float* beta1 = (const float*)d_in[6];
    const float* W2    = (const float*)d_in[7];
    const float* b2    = (const float*)d_in[8];
    const float* bng   = (const float*)d_in[9];
    const float* bnb   = (const float*)d_in[10];
    float* out = (float*)d_out;

    int n = in_sizes[0] / DD;
    int E = in_sizes[1] / 2;

    float* bufs = nullptr;
    cudaGetSymbolAddress((void**)&bufs, g_bufs);
    float* xn   = bufs;
    float* agg  = bufs + (size_t)1 * NMAX * DD;
    float* h    = bufs + (size_t)2 * NMAX * DD;
    float* xraw = bufs + (size_t)3 * NMAX * DD;

    cudaFuncSetAttribute((const void*)gemm_kernel,
                         cudaFuncAttributeMaxDynamicSharedMemorySize, GEMM_SMEM_BYTES);

    int nb256 = (n + 255) / 256;
    int eb256 = (E + 255) / 256;

    // --- one-time per launch: stats zero, dtype detect, CSR build ---
    zero_stats_kernel<<<1, 256>>>();
    detect_kernel<<<1, 32>>>((const int*)ei);
    zero_counts_kernel<<<nb256, 256>>>(n);
    hist_kernel<<<eb256, 256>>>(ei, E);
    scanA_kernel<<<nb256, 256>>>(n);
    scanB_kernel<<<1, 1024>>>(nb256);
    scanC2_kernel<<<nb256, 256>>>(n);
    place_kernel<<<eb256, 256>>>(ei, E);

    int prepBlocks = (n * (DD / 4) + 255) / 256;
    int aggBlocks = (n + 7) / 8;           // 8 warps/block, 1 node/warp
    int gemmBlocks = (n + 127) / 128;
    float invN = 1.0f / (float)n;

    const float* cur = x;   // activated features for this layer
    for (int layer = 0; layer < 3; layer++) {
        if (layer > 0) {
            prep_kernel<<<prepBlocks, 256>>>(xraw, xn, n);
            cur = xn;
        }
        agg_kernel<<<aggBlocks, 256>>>(cur, agg, eps, layer, n);
        gemm_kernel<<<gemmBlocks, 256, GEMM_SMEM_BYTES>>>(
            agg, W1 + (size_t)layer * DD * DD, b1 + layer * DD, h, n, 0, 1);
        bnparams_kernel<<<1, 128>>>(g1 + layer * DD, beta1 + layer * DD, invN);
        int last = (layer == 2);
        float* o = last ? out : xraw;
        gemm_kernel<<<gemmBlocks, 256, GEMM_SMEM_BYTES>>>(
            h, W2 + (size_t)layer * DD * DD, b2 + layer * DD, o, n, 1, last ? 0 : 1);
        if (!last)
            bnparams_kernel<<<1, 128>>>(bng + layer * DD, bnb + layer * DD, invN);
    }
}